// round 2
// baseline (speedup 1.0000x reference)
#include <cuda_runtime.h>
#include <stdint.h>

#define NEGF (-1e30f)

constexpr int T = 1024;
constexpr int B = 32;
constexpr int C = 96;
constexpr int W = 16;   // beam width
constexpr int P = 4;    // top paths

// ---------- key helpers: (score, index) -> 64-bit max-reducible key ----------
// Larger score wins; ties -> lower global candidate index wins (matches jax.lax.top_k).
__device__ __forceinline__ unsigned long long make_key(float f, int idx) {
    unsigned u = __float_as_uint(f);
    unsigned ord = (u & 0x80000000u) ? ~u : (u | 0x80000000u);
    return ((unsigned long long)ord << 11) | (unsigned long long)(2047 - idx);
}
__device__ __forceinline__ int key_idx(unsigned long long k) {
    return 2047 - (int)(k & 2047ULL);
}
__device__ __forceinline__ float key_score(unsigned long long k) {
    unsigned ord = (unsigned)(k >> 11);
    unsigned u = (ord & 0x80000000u) ? (ord ^ 0x80000000u) : ~ord;
    return __uint_as_float(u);
}
// logaddexp, same formula as jnp.logaddexp
__device__ __forceinline__ float lae(float a, float b) {
    float m = fmaxf(a, b);
    float d = fabsf(a - b);
    return m + log1pf(expf(-d));
}
__device__ __forceinline__ unsigned long long warp_max(unsigned long long v) {
    #pragma unroll
    for (int o = 16; o; o >>= 1) {
        unsigned long long w = __shfl_xor_sync(0xffffffffu, v, o);
        v = (w > v) ? w : v;
    }
    return v;
}

__global__ __launch_bounds__(512, 1)
void ctc_beam_kernel(const float* __restrict__ data,      // [T, B, C] log-probs
                     const int*   __restrict__ data_len,  // [B]
                     float*       __restrict__ out)       // [B*P] + [B*P] + [B*P*T]
{
    const int b    = blockIdx.x;
    const int tid  = threadIdx.x;
    const int lane = tid & 31;
    const int wid  = tid >> 5;          // 16 warps; warp w owns beam w
    const int len  = data_len[b];

    __shared__ float sh_lp[2][C];                       // double-buffered log-probs
    __shared__ float s_pb[2][W], s_pnb[2][W];           // ping-pong beam state
    __shared__ int   s_ln[2][W], s_last[2][W];
    __shared__ float s_spb[W], s_spnb[W];               // stay candidates
    __shared__ unsigned long long s_top[W][W];          // per-warp sorted top-16
    __shared__ unsigned short s_bp[T][W];               // backpointers: (parent<<8)|sym
    __shared__ int   s_selslot[P], s_sellen[P];
    __shared__ float s_selscore[P];

    // init state (buffer 0) + first lp row
    if (tid < W) {
        s_pb[0][tid]   = (tid == 0) ? 0.0f : NEGF;
        s_pnb[0][tid]  = NEGF;
        s_ln[0][tid]   = 0;
        s_last[0][tid] = -1;
    }
    if (tid < C) sh_lp[0][tid] = data[(size_t)(0 * B + b) * C + tid];
    __syncthreads();

    for (int t = 0; t < len; ++t) {
        const int buf = t & 1;

        // prefetch next timestep's log-probs (hides DRAM latency under compute)
        float pre = 0.0f;
        if (tid < C && (t + 1) < T)
            pre = data[(size_t)((t + 1) * B + b) * C + tid];

        // ---------------- phase 1: warp w -> local sorted top-16 of its 97 candidates
        {
            const int w  = wid;
            float pbw    = s_pb[buf][w];
            float pnbw   = s_pnb[buf][w];
            int   lw     = s_ln[buf][w];
            int   lastw  = s_last[buf][w];
            float ptot   = lae(pbw, pnbw);
            float spb    = ptot + sh_lp[buf][0];                       // blank emit
            int   li     = (lastw > 0) ? lastw : 0;
            float spnb   = (lw > 0) ? (pnbw + sh_lp[buf][li]) : NEGF;  // repeat last
            if (lane == 0) { s_spb[w] = spb; s_spnb[w] = spnb; }
            float sstay  = lae(spb, spnb);

            unsigned long long k0, k1, k2, k3;
            {   int c = lane;
                float sc = (c == 0) ? NEGF : (sh_lp[buf][c] + ((c == lastw) ? pbw : ptot));
                k0 = make_key(sc, W + w * C + c); }
            {   int c = lane + 32;
                float sc = sh_lp[buf][c] + ((c == lastw) ? pbw : ptot);
                k1 = make_key(sc, W + w * C + c); }
            {   int c = lane + 64;
                float sc = sh_lp[buf][c] + ((c == lastw) ? pbw : ptot);
                k2 = make_key(sc, W + w * C + c); }
            k3 = (lane == 0) ? make_key(sstay, w) : 0ULL;

            #pragma unroll 1
            for (int r = 0; r < W; ++r) {
                unsigned long long m  = (k0 > k1) ? k0 : k1;
                unsigned long long m2 = (k2 > k3) ? k2 : k3;
                m = (m > m2) ? m : m2;
                m = warp_max(m);
                if      (k0 == m) k0 = 0ULL;
                else if (k1 == m) k1 = 0ULL;
                else if (k2 == m) k2 = 0ULL;
                else if (k3 == m) k3 = 0ULL;
                if (lane == 0) s_top[w][r] = m;
            }
        }
        __syncthreads();

        // ---------------- phase 2+3: warp 0 merges 16 sorted lists, updates state
        if (wid == 0) {
            unsigned long long head = (lane < W) ? s_top[lane][0] : 0ULL;
            int ptr = 0;
            unsigned long long mywin = 0ULL;
            #pragma unroll 1
            for (int r = 0; r < W; ++r) {
                unsigned long long win = warp_max(head);
                if (head == win) {
                    ++ptr;
                    head = (ptr < W && lane < W) ? s_top[lane][ptr] : 0ULL;
                }
                if (lane == r) mywin = win;   // lane r keeps rank-r winner
            }
            if (lane < W) {
                int   idx   = key_idx(mywin);
                float score = key_score(mywin);
                int parent, sym, nlen, nlast;
                float npb, npnb;
                if (idx < W) {                 // stay
                    parent = idx; sym = 0xFF;
                    npb  = s_spb[parent];
                    npnb = s_spnb[parent];
                    nlen = s_ln[buf][parent];
                    nlast = s_last[buf][parent];
                } else {                       // extend with symbol c
                    int e = idx - W;
                    parent = e / C;
                    int c  = e - parent * C;
                    sym = c;
                    npb  = NEGF;
                    npnb = score;
                    nlen = s_ln[buf][parent] + 1;
                    nlast = c;
                }
                const int nb = buf ^ 1;
                s_pb[nb][lane]   = npb;
                s_pnb[nb][lane]  = npnb;
                s_ln[nb][lane]   = nlen;
                s_last[nb][lane] = nlast;
                s_bp[t][lane]    = (unsigned short)((parent << 8) | sym);
            }
        }
        // park prefetched lp row into the other buffer
        if (tid < C && (t + 1) < T) sh_lp[buf ^ 1][tid] = pre;
        __syncthreads();
    }

    // ---------------- final top-P over total beam probabilities
    if (wid == 0) {
        const int cb = len & 1;
        unsigned long long key = 0ULL;
        if (lane < W)
            key = make_key(lae(s_pb[cb][lane], s_pnb[cb][lane]), lane);
        #pragma unroll
        for (int r = 0; r < P; ++r) {
            unsigned long long win = warp_max(key);
            if (key == win) key = 0ULL;
            if (lane == 0) {
                int slot      = key_idx(win);
                s_selslot[r]  = slot;
                s_selscore[r] = key_score(win);
                s_sellen[r]   = s_ln[cb][slot];
            }
        }
    }
    __syncthreads();

    // ---------------- outputs (flattened, float32): -scores, lens, labels
    float* o_neg = out;                       // [B, P]
    float* o_len = out + B * P;               // [B, P]
    float* o_dec = out + 2 * B * P;           // [B, P, T]

    if (tid < P) {
        o_neg[b * P + tid] = -s_selscore[tid];
        o_len[b * P + tid] = (float)s_sellen[tid];
    }
    for (int i = tid; i < P * T; i += blockDim.x)
        o_dec[(size_t)b * P * T + i] = -1.0f;
    __syncthreads();

    // backtrack the P winning chains through the backpointer tree
    if (tid < P) {
        int slot = s_selslot[tid];
        int pos  = s_sellen[tid];
        float* dst = o_dec + ((size_t)b * P + tid) * T;
        for (int tt = len - 1; tt >= 0; --tt) {
            unsigned e = s_bp[tt][slot];
            int sym = e & 0xFF;
            slot    = e >> 8;
            if (sym != 0xFF) dst[--pos] = (float)sym;
        }
    }
}

extern "C" void kernel_launch(void* const* d_in, const int* in_sizes, int n_in,
                              void* d_out, int out_size) {
    const float* data = (const float*)d_in[0];
    const int*   dlen = (const int*)d_in[1];
    ctc_beam_kernel<<<B, 512>>>(data, dlen, (float*)d_out);
}

// round 3
// speedup vs baseline: 3.1137x; 3.1137x over previous
#include <cuda_runtime.h>
#include <stdint.h>

#define NEGF (-1e30f)

constexpr int T = 1024;
constexpr int B = 32;
constexpr int C = 96;
constexpr int W = 16;   // beam width
constexpr int P = 4;    // top paths
constexpr int S = 20;   // top lp columns kept per (b,t)

// scratch: per (b,t) the top-S non-blank lp columns as packed keys (ord(lp)<<7 | (127-c))
__device__ unsigned long long g_sorted[(size_t)B * T * S];

// ---------- key helpers ----------
__device__ __forceinline__ unsigned ford(float f) {
    unsigned u = __float_as_uint(f);
    return (u & 0x80000000u) ? ~u : (u | 0x80000000u);
}
__device__ __forceinline__ float funord(unsigned ord) {
    unsigned u = (ord & 0x80000000u) ? (ord ^ 0x80000000u) : ~ord;
    return __uint_as_float(u);
}
// candidate key: larger score wins; ties -> lower global index wins (matches jax.lax.top_k)
__device__ __forceinline__ unsigned long long make_key(float f, int idx) {
    return ((unsigned long long)ford(f) << 11) | (unsigned long long)(2047 - idx);
}
__device__ __forceinline__ int key_idx(unsigned long long k) { return 2047 - (int)(k & 2047ULL); }
__device__ __forceinline__ float key_score(unsigned long long k) { return funord((unsigned)(k >> 11)); }

// logaddexp, same formula as jnp.logaddexp
__device__ __forceinline__ float lae(float a, float b) {
    float m = fmaxf(a, b);
    float d = fabsf(a - b);
    return m + log1pf(expf(-d));
}
__device__ __forceinline__ unsigned long long warp_max(unsigned long long v) {
    #pragma unroll
    for (int o = 16; o; o >>= 1) {
        unsigned long long w = __shfl_xor_sync(0xffffffffu, v, o);
        v = (w > v) ? w : v;
    }
    return v;
}

// ============================================================================
// Kernel 1: per-(b,t) sort of non-blank lp columns, keep top-S. One warp each.
// Layout: element e = r*32 + lane  (e == column c initially).
// ============================================================================
__global__ __launch_bounds__(256)
void presort_kernel(const float* __restrict__ data)   // [T, B, C]
{
    int warp = (blockIdx.x * blockDim.x + threadIdx.x) >> 5;
    if (warp >= B * T) return;
    int b = warp / T, t = warp - b * T;
    int lane = threadIdx.x & 31;

    const float* row = data + ((size_t)t * B + b) * C;
    unsigned long long k[4];
    #pragma unroll
    for (int r = 0; r < 4; ++r) {
        int c = r * 32 + lane;
        if (c >= 1 && c < C)
            k[r] = ((unsigned long long)ford(row[c]) << 7) | (unsigned long long)(127 - c);
        else
            k[r] = 0ULL;   // blank + padding sink to bottom
    }

    // bitonic sort of 128 keys, descending
    #pragma unroll
    for (int k2 = 2; k2 <= 128; k2 <<= 1) {
        #pragma unroll
        for (int j = 64; j > 0; j >>= 1) {
            if (j >= k2) continue;
            if (j >= 32) {                       // register-local compare-exchange
                int rj = j >> 5;
                #pragma unroll
                for (int r = 0; r < 4; ++r) {
                    if ((r & rj) == 0) {
                        int pr = r | rj;
                        bool desc = (((r * 32) & k2) == 0);   // lane bits don't reach k2>=64
                        unsigned long long a = k[r], c2 = k[pr];
                        unsigned long long mx = a > c2 ? a : c2;
                        unsigned long long mn = a > c2 ? c2 : a;
                        k[r]  = desc ? mx : mn;
                        k[pr] = desc ? mn : mx;
                    }
                }
            } else {                              // cross-lane compare-exchange
                #pragma unroll
                for (int r = 0; r < 4; ++r) {
                    unsigned long long o = __shfl_xor_sync(0xffffffffu, k[r], j);
                    int e = r * 32 + lane;
                    bool takemax = ((e & k2) == 0) == ((lane & j) == 0);
                    bool bigger  = k[r] > o;
                    k[r] = (takemax == bigger) ? k[r] : o;
                }
            }
        }
    }
    // sorted desc: elements 0..31 live in k[0] at lane==e
    if (lane < S)
        g_sorted[((size_t)b * T + t) * S + lane] = k[0];
}

// ============================================================================
// Kernel 2: sequential beam search, one CTA per batch element, warp w = beam w.
// ============================================================================
__global__ __launch_bounds__(512, 1)
void ctc_beam_kernel(const float* __restrict__ data,      // [T, B, C] log-probs
                     const int*   __restrict__ data_len,  // [B]
                     float*       __restrict__ out)       // [B*P] + [B*P] + [B*P*T]
{
    const int b    = blockIdx.x;
    const int tid  = threadIdx.x;
    const int lane = tid & 31;
    const int wid  = tid >> 5;
    const int len  = data_len[b];

    __shared__ float sh_lp[2][C];
    __shared__ unsigned long long sh_srt[2][S];
    __shared__ float s_pb[2][W], s_pnb[2][W];
    __shared__ int   s_ln[2][W], s_last[2][W];
    __shared__ float s_spb[W], s_spnb[W];
    __shared__ unsigned long long s_top[W][W];
    __shared__ unsigned short s_bp[T][W];                 // (parent<<8)|sym, 0xFF = stay
    __shared__ int   s_selslot[P], s_sellen[P];
    __shared__ float s_selscore[P];

    if (tid < W) {
        s_pb[0][tid]   = (tid == 0) ? 0.0f : NEGF;
        s_pnb[0][tid]  = NEGF;
        s_ln[0][tid]   = 0;
        s_last[0][tid] = -1;
    }
    if (tid < C) sh_lp[0][tid] = data[(size_t)b * C + tid];
    if (tid >= C && tid < C + S) sh_srt[0][tid - C] = g_sorted[((size_t)b * T) * S + (tid - C)];
    __syncthreads();

    for (int t = 0; t < len; ++t) {
        const int buf = t & 1;

        // prefetch next timestep
        float pre = 0.0f;
        unsigned long long pres = 0ULL;
        if (t + 1 < T) {
            if (tid < C) pre = data[(size_t)((t + 1) * B + b) * C + tid];
            else if (tid < C + S) pres = g_sorted[((size_t)b * T + (t + 1)) * S + (tid - C)];
        }

        // -------- phase 1: warp w builds & sorts its 21 candidates --------
        {
            const int w  = wid;
            float pbw    = s_pb[buf][w];
            float pnbw   = s_pnb[buf][w];
            int   lw     = s_ln[buf][w];
            int   lastw  = s_last[buf][w];
            float ptot   = lae(pbw, pnbw);
            float spb    = ptot + sh_lp[buf][0];
            int   li     = (lw > 0) ? lastw : 0;
            float spnb   = (lw > 0) ? (pnbw + sh_lp[buf][li]) : NEGF;
            if (lane == 0) { s_spb[w] = spb; s_spnb[w] = spnb; }
            float sstay  = lae(spb, spnb);

            unsigned long long key = 0ULL;
            if (lane < S) {
                unsigned long long sk = sh_srt[buf][lane];
                int   c   = 127 - (int)(sk & 127ULL);
                float lpc = funord((unsigned)(sk >> 7));
                float sc  = lpc + ((c == lastw) ? pbw : ptot);
                key = make_key(sc, W + w * C + c);
            } else if (lane == S) {
                key = make_key(sstay, w);
            }

            // bitonic sort 32, descending
            #pragma unroll
            for (int k2 = 2; k2 <= 32; k2 <<= 1) {
                #pragma unroll
                for (int j = k2 >> 1; j > 0; j >>= 1) {
                    unsigned long long o = __shfl_xor_sync(0xffffffffu, key, j);
                    bool takemax = ((lane & k2) == 0) == ((lane & j) == 0);
                    bool bigger  = key > o;
                    key = (takemax == bigger) ? key : o;
                }
            }
            if (lane < W) s_top[w][lane] = key;
        }
        __syncthreads();

        // -------- phase 2: warp 0 bitonic-merges 16 sorted 16-lists --------
        if (wid == 0) {
            unsigned long long m[8];
            const int rr = lane & 15;
            const int h  = lane >> 4;
            #pragma unroll
            for (int q = 0; q < 8; ++q) m[q] = s_top[2 * q + h][rr];

            #pragma unroll
            for (int lvl = 0; lvl < 4; ++lvl) {
                const int nreg = 8 >> lvl;
                #pragma unroll
                for (int q = 0; q < 8; ++q) {
                    if (q >= nreg) break;
                    // top-16 of two sorted desc lists: max(a[i], b[15-i]) via lane^31
                    unsigned long long o = __shfl_xor_sync(0xffffffffu, m[q], 31);
                    unsigned long long v = (m[q] > o) ? m[q] : o;   // bitonic in each half
                    #pragma unroll
                    for (int j = 8; j > 0; j >>= 1) {               // clean -> sorted desc
                        unsigned long long o2 = __shfl_xor_sync(0xffffffffu, v, j);
                        bool takemax = ((lane & j) == 0);
                        bool bigger  = v > o2;
                        v = (takemax == bigger) ? v : o2;
                    }
                    m[q] = v;   // sorted desc in lanes 0-15, mirrored copy in 16-31
                }
                // repack: list pair (2q,2q+1) -> halves of reg q (mirror copy is free)
                #pragma unroll
                for (int q = 0; q < 4; ++q) {
                    if (q >= (nreg >> 1)) break;
                    m[q] = (lane < 16) ? m[2 * q] : m[2 * q + 1];
                }
            }

            if (lane < W) {
                unsigned long long mywin = m[0];       // rank-`lane` global winner
                int   idx   = key_idx(mywin);
                float score = key_score(mywin);
                int parent, sym, nlen, nlast;
                float npb, npnb;
                if (idx < W) {                          // stay
                    parent = idx; sym = 0xFF;
                    npb   = s_spb[parent];
                    npnb  = s_spnb[parent];
                    nlen  = s_ln[buf][parent];
                    nlast = s_last[buf][parent];
                } else {                                // extend with symbol c
                    int e  = idx - W;
                    parent = e / C;
                    int c  = e - parent * C;
                    sym   = c;
                    npb   = NEGF;
                    npnb  = score;
                    nlen  = s_ln[buf][parent] + 1;
                    nlast = c;
                }
                const int nb = buf ^ 1;
                s_pb[nb][lane]   = npb;
                s_pnb[nb][lane]  = npnb;
                s_ln[nb][lane]   = nlen;
                s_last[nb][lane] = nlast;
                s_bp[t][lane]    = (unsigned short)((parent << 8) | sym);
            }
        }
        // park prefetched rows
        if (t + 1 < T) {
            if (tid < C) sh_lp[buf ^ 1][tid] = pre;
            else if (tid < C + S) sh_srt[buf ^ 1][tid - C] = pres;
        }
        __syncthreads();
    }

    // -------- final top-P over total beam probabilities --------
    if (wid == 0) {
        const int cb = len & 1;
        unsigned long long key = 0ULL;
        if (lane < W)
            key = make_key(lae(s_pb[cb][lane], s_pnb[cb][lane]), lane);
        #pragma unroll
        for (int r = 0; r < P; ++r) {
            unsigned long long win = warp_max(key);
            if (key == win) key = 0ULL;
            if (lane == 0) {
                int slot      = key_idx(win);
                s_selslot[r]  = slot;
                s_selscore[r] = key_score(win);
                s_sellen[r]   = s_ln[cb][slot];
            }
        }
    }
    __syncthreads();

    // -------- outputs (flattened float32): -scores, lens, labels --------
    float* o_neg = out;
    float* o_len = out + B * P;
    float* o_dec = out + 2 * B * P;

    if (tid < P) {
        o_neg[b * P + tid] = -s_selscore[tid];
        o_len[b * P + tid] = (float)s_sellen[tid];
    }
    for (int i = tid; i < P * T; i += blockDim.x)
        o_dec[(size_t)b * P * T + i] = -1.0f;
    __syncthreads();

    if (tid < P) {
        int slot = s_selslot[tid];
        int pos  = s_sellen[tid];
        float* dst = o_dec + ((size_t)b * P + tid) * T;
        for (int tt = len - 1; tt >= 0; --tt) {
            unsigned e = s_bp[tt][slot];
            int sym = e & 0xFF;
            slot    = e >> 8;
            if (sym != 0xFF) dst[--pos] = (float)sym;
        }
    }
}

extern "C" void kernel_launch(void* const* d_in, const int* in_sizes, int n_in,
                              void* d_out, int out_size) {
    const float* data = (const float*)d_in[0];
    const int*   dlen = (const int*)d_in[1];
    presort_kernel<<<(B * T + 7) / 8, 256>>>(data);
    ctc_beam_kernel<<<B, 512>>>(data, dlen, (float*)d_out);
}